// round 1
// baseline (speedup 1.0000x reference)
#include <cuda_runtime.h>

// Problem constants (fixed by the reference):
//   B=16, C=2048, H=2, HS=64, HOD=1, D_MODEL=2
// Collapsed formulation:
//   xp[b,f] = x[b,f] + (sin f, cos f)                      (pe with d_model=2: div=1)
//   M_h   = Wq_h @ Wk_h^T            (2x2)
//   g_h   = Wv_h @ Wo_h[:,0]         (2,)
//   s(c,f)= xp_c^T M_h xp_f / sqrt(64)
//   o_h(c)= sum_{f<=c} softmax(s)_f * (g_h . xp_f)
//   out(c,j) = o_0*Wb[0,j] + o_1*Wb[1,j]

#define CC   2048
#define NTHR 256

__device__ __forceinline__ float ex2f(float v) {
    float y;
    asm("ex2.approx.ftz.f32 %0, %1;" : "=f"(y) : "f"(v));
    return y;
}

__global__ __launch_bounds__(NTHR, 1)
void mha_collapsed_kernel(const float* __restrict__ x,
                          const float* __restrict__ Wq,
                          const float* __restrict__ Wk,
                          const float* __restrict__ Wv,
                          const float* __restrict__ Wo,
                          const float* __restrict__ Wb,
                          float* __restrict__ out)
{
    __shared__ float4 sh[CC];      // per-f: {x0, x1, u0, u1}  (32 KB)
    __shared__ float  sM[2][2][2]; // M[h][i][j]
    __shared__ float  sG[2][2];    // g[h][i]
    __shared__ int    sA[2];       // bit-pattern max of |x0|, |x1|

    const int tid = threadIdx.x;
    const int b   = blockIdx.x >> 3;  // batch
    const int r   = blockIdx.x & 7;   // row-group phase

    if (tid < 2) sA[tid] = 0;

    // ---- 12 length-64 dot products (8 for M, 4 for g), one per 16-lane group ----
    if (tid < 192) {
        const int grp = tid >> 4, l16 = tid & 15;
        const float *pa, *pb;
        if (grp < 8) {
            const int h = grp >> 2, i = (grp >> 1) & 1, j = grp & 1;
            pa = Wq + h * 128 + i * 64;
            pb = Wk + h * 128 + j * 64;
        } else {
            const int g2 = grp - 8, h = g2 >> 1, i = g2 & 1;
            pa = Wv + h * 128 + i * 64;
            pb = Wo + h * 64;             // HOD==1 -> contiguous
        }
        float s = 0.f;
        #pragma unroll
        for (int e = 0; e < 4; ++e) s = fmaf(pa[l16 * 4 + e], pb[l16 * 4 + e], s);
        #pragma unroll
        for (int off = 8; off; off >>= 1) s += __shfl_down_sync(0xffffffffu, s, off, 16);
        if (l16 == 0) {
            if (grp < 8) sM[grp >> 2][(grp >> 1) & 1][grp & 1] = s;
            else         sG[(grp - 8) >> 1][(grp - 8) & 1]     = s;
        }
    }

    // ---- fill xp into shared + track per-thread |x| maxima ----
    const float2* xin = reinterpret_cast<const float2*>(x) + b * CC;
    float amax0 = 0.f, amax1 = 0.f;
    for (int f = tid; f < CC; f += NTHR) {
        const float2 v = xin[f];
        const float fp = (float)f;
        const float x0 = v.x + sinf(fp);
        const float x1 = v.y + cosf(fp);
        sh[f] = make_float4(x0, x1, 0.f, 0.f);
        amax0 = fmaxf(amax0, fabsf(x0));
        amax1 = fmaxf(amax1, fabsf(x1));
    }
    __syncthreads();

    // block max (nonneg floats: int compare == float compare)
    #pragma unroll
    for (int off = 16; off; off >>= 1) {
        amax0 = fmaxf(amax0, __shfl_down_sync(0xffffffffu, amax0, off));
        amax1 = fmaxf(amax1, __shfl_down_sync(0xffffffffu, amax1, off));
    }
    if ((tid & 31) == 0) {
        atomicMax(&sA[0], __float_as_int(amax0));
        atomicMax(&sA[1], __float_as_int(amax1));
    }

    // ---- payloads u_h(f) = g_h . xp_f ----
    {
        const float g00 = sG[0][0], g01 = sG[0][1];
        const float g10 = sG[1][0], g11 = sG[1][1];
        for (int f = tid; f < CC; f += NTHR) {
            float4 t = sh[f];
            t.z = fmaf(g00, t.x, g01 * t.y);
            t.w = fmaf(g10, t.x, g11 * t.y);
            sh[f] = t;
        }
    }
    __syncthreads();

    // ---- main: one query per thread; mirrored warp pairing balances SMSPs ----
    const float A0 = __int_as_float(sA[0]);
    const float A1 = __int_as_float(sA[1]);
    const int k    = tid >> 5, lane = tid & 31;
    const int w    = (k < 4) ? (8 * k + r) : (63 - (8 * (k - 4) + r));
    const int c    = 32 * w + lane;

    const float4 xc = sh[c];
    const float SCL = 0.18033688011112042f;  // log2(e)/sqrt(64)
    // p_h = M_h^T xp_c, pre-scaled into log2 units
    const float P00 = fmaf(sM[0][0][0], xc.x, sM[0][1][0] * xc.y) * SCL;
    const float P01 = fmaf(sM[0][0][1], xc.x, sM[0][1][1] * xc.y) * SCL;
    const float P10 = fmaf(sM[1][0][0], xc.x, sM[1][1][0] * xc.y) * SCL;
    const float P11 = fmaf(sM[1][0][1], xc.x, sM[1][1][1] * xc.y) * SCL;
    // upper bound on the (log2-scaled) score -> ex2 args <= 0, no overflow
    const float nm0 = -(fabsf(P00) * A0 + fabsf(P01) * A1);
    const float nm1 = -(fabsf(P10) * A0 + fabsf(P11) * A1);

    float den0 = 0.f, num0 = 0.f, den1 = 0.f, num1 = 0.f;
    const int fmain = 32 * w;  // all lanes valid for f < fmain (c >= fmain)

    #pragma unroll 4
    for (int f = 0; f < fmain; ++f) {
        const float4 t = sh[f];
        const float e0 = ex2f(fmaf(t.x, P00, fmaf(t.y, P01, nm0)));
        const float e1 = ex2f(fmaf(t.x, P10, fmaf(t.y, P11, nm1)));
        den0 += e0; num0 = fmaf(e0, t.z, num0);
        den1 += e1; num1 = fmaf(e1, t.w, num1);
    }
    // causal tail: per-lane bound, <=32 iterations
    for (int f = fmain; f <= c; ++f) {
        const float4 t = sh[f];
        const float e0 = ex2f(fmaf(t.x, P00, fmaf(t.y, P01, nm0)));
        const float e1 = ex2f(fmaf(t.x, P10, fmaf(t.y, P11, nm1)));
        den0 += e0; num0 = fmaf(e0, t.z, num0);
        den1 += e1; num1 = fmaf(e1, t.w, num1);
    }

    const float o0 = num0 / den0;
    const float o1 = num1 / den1;
    const float b00 = __ldg(Wb + 0), b01 = __ldg(Wb + 1);
    const float b10 = __ldg(Wb + 2), b11 = __ldg(Wb + 3);
    float2 res;
    res.x = fmaf(o0, b00, o1 * b10);
    res.y = fmaf(o0, b01, o1 * b11);
    reinterpret_cast<float2*>(out)[b * CC + c] = res;
}

extern "C" void kernel_launch(void* const* d_in, const int* in_sizes, int n_in,
                              void* d_out, int out_size)
{
    const float* x  = (const float*)d_in[0];
    const float* Wq = (const float*)d_in[1];
    const float* Wk = (const float*)d_in[2];
    const float* Wv = (const float*)d_in[3];
    const float* Wo = (const float*)d_in[4];
    const float* Wb = (const float*)d_in[5];
    float* out = (float*)d_out;

    // 16 batches x 8 row-group phases = 128 blocks (single wave), 256 thr each.
    mha_collapsed_kernel<<<128, NTHR>>>(x, Wq, Wk, Wv, Wo, Wb, out);
}

// round 3
// speedup vs baseline: 1.6242x; 1.6242x over previous
#include <cuda_runtime.h>

// B=16, C=2048, H=2, HS=64, HOD=1, D_MODEL=2
// Collapsed: M_h = Wq_h Wk_h^T (2x2), g_h = Wv_h Wo_h (2,)
//   s(c,f) = xp_c^T M_h xp_f / 8;  o_h(c) = softmax-weighted sum of (g_h . xp_f)
// 1024 threads: 8 query rows x 4 f-splits per block; partials summed by
// REUSING the first 16KB of sh[] after the main loop (stays under 48KB static).

#define CC   2048
#define NTHR 1024

__device__ __forceinline__ float ex2f(float v) {
    float y;
    asm("ex2.approx.ftz.f32 %0, %1;" : "=f"(y) : "f"(v));
    return y;
}

__global__ __launch_bounds__(NTHR, 1)
void mha_collapsed_kernel(const float* __restrict__ x,
                          const float* __restrict__ Wq,
                          const float* __restrict__ Wk,
                          const float* __restrict__ Wv,
                          const float* __restrict__ Wo,
                          const float* __restrict__ Wb,
                          float* __restrict__ out)
{
    __shared__ float4 sh[CC];      // per-f: {x0, x1, u0, u1}  (32 KB); reused for partials
    __shared__ float  sM[2][2][2]; // M[h][i][j]
    __shared__ float  sG[2][2];    // g[h][i]
    __shared__ int    sA[2];       // bit-pattern max of |x0|, |x1|

    const int tid = threadIdx.x;
    const int b   = blockIdx.x >> 3;   // batch
    const int r   = blockIdx.x & 7;    // row-group phase

    if (tid < 2) sA[tid] = 0;

    // ---- 12 length-64 dot products (8 for M, 4 for g), one per 16-lane group ----
    if (tid < 192) {
        const int grp = tid >> 4, l16 = tid & 15;
        const float *pa, *pb;
        if (grp < 8) {
            const int h = grp >> 2, i = (grp >> 1) & 1, j = grp & 1;
            pa = Wq + h * 128 + i * 64;
            pb = Wk + h * 128 + j * 64;
        } else {
            const int g2 = grp - 8, h = g2 >> 1, i = g2 & 1;
            pa = Wv + h * 128 + i * 64;
            pb = Wo + h * 64;              // HOD==1 -> contiguous
        }
        float s = 0.f;
        #pragma unroll
        for (int e = 0; e < 4; ++e) s = fmaf(pa[l16 * 4 + e], pb[l16 * 4 + e], s);
        #pragma unroll
        for (int off = 8; off; off >>= 1) s += __shfl_down_sync(0xffffffffu, s, off, 16);
        if (l16 == 0) {
            if (grp < 8) sM[grp >> 2][(grp >> 1) & 1][grp & 1] = s;
            else         sG[(grp - 8) >> 1][(grp - 8) & 1]     = s;
        }
    }

    // ---- fill xp into shared + track |x| maxima ----
    const float2* xin = reinterpret_cast<const float2*>(x) + b * CC;
    float amax0 = 0.f, amax1 = 0.f;
    for (int f = tid; f < CC; f += NTHR) {
        const float2 v = xin[f];
        const float fp = (float)f;
        const float x0 = v.x + sinf(fp);
        const float x1 = v.y + cosf(fp);
        sh[f] = make_float4(x0, x1, 0.f, 0.f);
        amax0 = fmaxf(amax0, fabsf(x0));
        amax1 = fmaxf(amax1, fabsf(x1));
    }
    __syncthreads();

    #pragma unroll
    for (int off = 16; off; off >>= 1) {
        amax0 = fmaxf(amax0, __shfl_down_sync(0xffffffffu, amax0, off));
        amax1 = fmaxf(amax1, __shfl_down_sync(0xffffffffu, amax1, off));
    }
    if ((tid & 31) == 0) {
        atomicMax(&sA[0], __float_as_int(amax0));   // nonneg: int cmp == float cmp
        atomicMax(&sA[1], __float_as_int(amax1));
    }

    // ---- payloads u_h(f) = g_h . xp_f ----
    {
        const float g00 = sG[0][0], g01 = sG[0][1];
        const float g10 = sG[1][0], g11 = sG[1][1];
        for (int f = tid; f < CC; f += NTHR) {
            float4 t = sh[f];
            t.z = fmaf(g00, t.x, g01 * t.y);
            t.w = fmaf(g10, t.x, g11 * t.y);
            sh[f] = t;
        }
    }
    __syncthreads();

    // ---- main: warp = (row slot j, f-split s); all lanes scan same f (LDS broadcast)
    const float A0 = __int_as_float(sA[0]);
    const float A1 = __int_as_float(sA[1]);
    const int wid  = tid >> 5, lane = tid & 31;
    const int j    = wid >> 2;        // row slot 0..7
    const int s    = wid & 3;         // f-split 0..3  (== SMSP id -> auto-balanced)
    const int w    = (j < 4) ? (8 * j + r) : (63 - (8 * (j - 4) + r));
    const int c    = 32 * w + lane;

    const float4 xc = sh[c];
    const float SCL = 0.18033688011112042f;  // log2(e)/sqrt(64)
    const float P00 = fmaf(sM[0][0][0], xc.x, sM[0][1][0] * xc.y) * SCL;
    const float P01 = fmaf(sM[0][0][1], xc.x, sM[0][1][1] * xc.y) * SCL;
    const float P10 = fmaf(sM[1][0][0], xc.x, sM[1][1][0] * xc.y) * SCL;
    const float P11 = fmaf(sM[1][0][1], xc.x, sM[1][1][1] * xc.y) * SCL;
    const float nm0 = -(fabsf(P00) * A0 + fabsf(P01) * A1);  // ex2 args <= 0
    const float nm1 = -(fabsf(P10) * A0 + fabsf(P11) * A1);

    float den0 = 0.f, num0 = 0.f, den1 = 0.f, num1 = 0.f;

    const int L  = 8 * w + 8;                 // chunk length = (32w+32)/4
    const int lo = s * L;
    const int hi = lo + L;
    int hiu = 32 * w + 1;                     // f < hiu valid for ALL lanes
    if (hiu > hi) hiu = hi;
    if (hiu < lo) hiu = lo;

    #pragma unroll 4
    for (int f = lo; f < hiu; ++f) {          // unmasked region
        const float4 t = sh[f];
        const float e0 = ex2f(fmaf(t.x, P00, fmaf(t.y, P01, nm0)));
        const float e1 = ex2f(fmaf(t.x, P10, fmaf(t.y, P11, nm1)));
        den0 += e0; num0 = fmaf(e0, t.z, num0);
        den1 += e1; num1 = fmaf(e1, t.w, num1);
    }
    #pragma unroll 2
    for (int f = hiu; f < hi; ++f) {          // diagonal region: causal mask
        const float4 t = sh[f];
        const float e0 = ex2f(fmaf(t.x, P00, fmaf(t.y, P01, nm0)));
        const float e1 = ex2f(fmaf(t.x, P10, fmaf(t.y, P11, nm1)));
        if (f <= c) {
            den0 += e0; num0 = fmaf(e0, t.z, num0);
            den1 += e1; num1 = fmaf(e1, t.w, num1);
        }
    }

    // ---- combine: reuse sh[0..1023] as the partials buffer ----
    __syncthreads();                          // everyone done READING sh
    sh[wid * 32 + lane] = make_float4(den0, num0, den1, num1);
    __syncthreads();

    if (s == 0) {
        const float4 p0 = sh[(wid + 0) * 32 + lane];
        const float4 p1 = sh[(wid + 1) * 32 + lane];
        const float4 p2 = sh[(wid + 2) * 32 + lane];
        const float4 p3 = sh[(wid + 3) * 32 + lane];
        const float D0 = p0.x + p1.x + p2.x + p3.x;
        const float N0 = p0.y + p1.y + p2.y + p3.y;
        const float D1 = p0.z + p1.z + p2.z + p3.z;
        const float N1 = p0.w + p1.w + p2.w + p3.w;
        const float o0 = N0 / D0;
        const float o1 = N1 / D1;
        const float b00 = __ldg(Wb + 0), b01 = __ldg(Wb + 1);
        const float b10 = __ldg(Wb + 2), b11 = __ldg(Wb + 3);
        float2 res;
        res.x = fmaf(o0, b00, o1 * b10);
        res.y = fmaf(o0, b01, o1 * b11);
        reinterpret_cast<float2*>(out)[b * CC + c] = res;
    }
}

extern "C" void kernel_launch(void* const* d_in, const int* in_sizes, int n_in,
                              void* d_out, int out_size)
{
    const float* x  = (const float*)d_in[0];
    const float* Wq = (const float*)d_in[1];
    const float* Wk = (const float*)d_in[2];
    const float* Wv = (const float*)d_in[3];
    const float* Wo = (const float*)d_in[4];
    const float* Wb = (const float*)d_in[5];
    float* out = (float*)d_out;

    mha_collapsed_kernel<<<128, NTHR>>>(x, Wq, Wk, Wv, Wo, Wb, out);
}

// round 5
// speedup vs baseline: 2.3449x; 1.4437x over previous
#include <cuda_runtime.h>

// B=16, C=2048, H=2, HS=64, HOD=1, D_MODEL=2
// Collapsed: M_h = Wq_h Wk_h^T (2x2), g_h = Wv_h Wo_h (2,)
//   t(c,f) = xp_c^T M_h xp_f / 8  (nats);  o_h(c) = sum_{f<=c} e^t (g_h.xp_f) / sum e^t
// Taylor:  e^{p.y} = sum_{j+i<=12} (p0^j/j!)(p1^i/i!) y0^j y1^i  (|t| <~ 1.3)
// => causal sums reduce to prefix moments M_{j,i}(c) = sum_{f<=c} y0^j y1^i.
// K1: per-(batch,chunk) raw moments (j+i<=13, 105 values) -> global scratch.
// K2: prefix-scan chunks, polynomial eval per query + exact-exp tail in own chunk.

#define CC     2048
#define NCHUNK 16
#define CHUNKF 128
#define NMOM   105          // #{(j,i): j+i<=13}
#define LOG2E  1.4426950408889634f

__device__ float g_mom[16][NCHUNK][NMOM];   // raw per-chunk moments

__device__ __forceinline__ int midx(int j, int i) {
    return j * 14 - (j * (j - 1)) / 2 + i;
}

__device__ __forceinline__ float ex2f(float v) {
    float y;
    asm("ex2.approx.ftz.f32 %0, %1;" : "=f"(y) : "f"(v));
    return y;
}

// ---------------- K1: chunk moments ----------------
// grid = 256 (chunk = bid&15, batch = bid>>4), 448 threads (14 warps).
// Warp j accumulates column {(j, i): i <= 13-j}; lane handles 4 f's.
__global__ __launch_bounds__(448, 1)
void k1_moments(const float* __restrict__ x)
{
    const int chunk = blockIdx.x & 15;
    const int b     = blockIdx.x >> 4;
    const int wid   = threadIdx.x >> 5, lane = threadIdx.x & 31;
    const int j     = wid;              // 0..13

    float acc[14];
    #pragma unroll
    for (int i = 0; i < 14; ++i) acc[i] = 0.f;

    #pragma unroll
    for (int ff = 0; ff < 4; ++ff) {
        const int f = chunk * CHUNKF + ff * 32 + lane;
        const float2 v = reinterpret_cast<const float2*>(x)[b * CC + f];
        const float y0 = v.x + sinf((float)f);
        const float y1 = v.y + cosf((float)f);
        float c0 = 1.f;
        for (int jj = 0; jj < j; ++jj) c0 *= y0;   // y0^j
        float vv = c0;
        #pragma unroll
        for (int i = 0; i < 14; ++i) { acc[i] += vv; vv *= y1; }
    }
    #pragma unroll
    for (int i = 0; i < 14; ++i) {
        float s = acc[i];
        #pragma unroll
        for (int off = 16; off; off >>= 1) s += __shfl_down_sync(0xffffffffu, s, off);
        acc[i] = s;
    }
    if (lane == 0) {
        for (int i = 0; i + j <= 13; ++i)
            g_mom[b][chunk][midx(j, i)] = acc[i];
    }
}

// ---------------- K2: evaluation ----------------
// grid = 128 (batch = bid>>3, phase r = bid&7); 1024 threads.
// c = r*256 + (tid&255).  sub = tid>>8: {0: h0-poly, 1: h1-poly, 2: h0-direct, 3: h1-direct}
__global__ __launch_bounds__(1024, 1)
void k2_eval(const float* __restrict__ x,
             const float* __restrict__ Wq,
             const float* __restrict__ Wk,
             const float* __restrict__ Wv,
             const float* __restrict__ Wo,
             const float* __restrict__ Wb,
             float* __restrict__ out)
{
    __shared__ float2 sY[256];          // xp for f in [256r, 256r+256)
    __shared__ float  sPa[NMOM];        // prefix over chunks < 2r
    __shared__ float  sPb[NMOM];        // prefix over chunks < 2r+1
    __shared__ float  sM[2][2][2];      // M[h][i][j]
    __shared__ float  sG[2][2];         // g[h][i]
    __shared__ float4 sPart[256][4];    // per-(c,sub) partials {den, a0, a1}
    __shared__ float2 sO[256];          // o per head

    const int tid = threadIdx.x;
    const int b   = blockIdx.x >> 3;
    const int r   = blockIdx.x & 7;

    // 12 length-64 dot products for M and g (16 lanes each)
    if (tid < 192) {
        const int grp = tid >> 4, l16 = tid & 15;
        const float *pa, *pb;
        if (grp < 8) {
            const int h = grp >> 2, i = (grp >> 1) & 1, jj = grp & 1;
            pa = Wq + h * 128 + i * 64;
            pb = Wk + h * 128 + jj * 64;
        } else {
            const int g2 = grp - 8, h = g2 >> 1, i = g2 & 1;
            pa = Wv + h * 128 + i * 64;
            pb = Wo + h * 64;
        }
        float s = 0.f;
        #pragma unroll
        for (int e = 0; e < 4; ++e) s = fmaf(pa[l16 * 4 + e], pb[l16 * 4 + e], s);
        #pragma unroll
        for (int off = 8; off; off >>= 1) s += __shfl_down_sync(0xffffffffu, s, off, 16);
        if (l16 == 0) {
            if (grp < 8) sM[grp >> 2][(grp >> 1) & 1][grp & 1] = s;
            else         sG[(grp - 8) >> 1][(grp - 8) & 1]     = s;
        }
    }
    // xp window
    if (tid < 256) {
        const int f = r * 256 + tid;
        const float2 v = reinterpret_cast<const float2*>(x)[b * CC + f];
        sY[tid] = make_float2(v.x + sinf((float)f), v.y + cosf((float)f));
    }
    // prefix moments over chunks
    if (tid >= 256 && tid < 256 + NMOM) {
        const int m = tid - 256;
        float s = 0.f;
        for (int k = 0; k < 2 * r; ++k) s += g_mom[b][k][m];
        sPa[m] = s;
        sPb[m] = s + g_mom[b][2 * r][m];
    }
    __syncthreads();

    const int c_loc = tid & 255;
    const int sub   = tid >> 8;
    const int h     = sub & 1;
    const int type  = sub >> 1;         // 0 = poly, 1 = direct
    const int c     = r * 256 + c_loc;

    const float2 yc = sY[c_loc];
    const float p0 = (sM[h][0][0] * yc.x + sM[h][1][0] * yc.y) * 0.125f;
    const float p1 = (sM[h][0][1] * yc.x + sM[h][1][1] * yc.y) * 0.125f;

    if (type == 0) {
        // polynomial part: sums over f < 128*chunk(c)
        const float INV[13] = {0.f, 1.f, 0.5f, 1.f/3.f, 0.25f, 0.2f, 1.f/6.f,
                               1.f/7.f, 0.125f, 1.f/9.f, 0.1f, 1.f/11.f, 1.f/12.f};
        float q0[13], q1[13];
        q0[0] = 1.f; q1[0] = 1.f;
        #pragma unroll
        for (int jj = 1; jj < 13; ++jj) {
            q0[jj] = q0[jj - 1] * p0 * INV[jj];
            q1[jj] = q1[jj - 1] * p1 * INV[jj];
        }
        const float* PRE = (c_loc & 128) ? sPb : sPa;
        float sd = 0.f, s0 = 0.f, s1 = 0.f;
        #pragma unroll
        for (int jj = 0; jj <= 12; ++jj) {
            #pragma unroll
            for (int ii = 0; ii + jj <= 12; ++ii) {
                const float w = q0[jj] * q1[ii];
                sd = fmaf(w, PRE[midx(jj, ii)],     sd);
                s0 = fmaf(w, PRE[midx(jj + 1, ii)], s0);
                s1 = fmaf(w, PRE[midx(jj, ii + 1)], s1);
            }
        }
        sPart[c_loc][sub] = make_float4(sd, s0, s1, 0.f);
    } else {
        // exact tail over f in [128*chunk(c), c]
        const int fstart = c & ~127;
        const float pd0 = p0 * LOG2E, pd1 = p1 * LOG2E;
        float den = 0.f, a0 = 0.f, a1 = 0.f;
        for (int f = fstart; f <= c; ++f) {
            const float2 yf = sY[f - r * 256];
            const float e = ex2f(fmaf(yf.x, pd0, yf.y * pd1));
            den += e;
            a0 = fmaf(e, yf.x, a0);
            a1 = fmaf(e, yf.y, a1);
        }
        sPart[c_loc][sub] = make_float4(den, a0, a1, 0.f);
    }
    __syncthreads();

    if (type == 0) {
        const float4 mine = sPart[c_loc][sub];
        const float4 dd   = sPart[c_loc][2 + h];
        const float den = mine.x + dd.x;
        const float A0  = mine.y + dd.y;
        const float A1  = mine.z + dd.z;
        const float num = sG[h][0] * A0 + sG[h][1] * A1;
        const float o   = num / den;
        if (h == 0) sO[c_loc].x = o; else sO[c_loc].y = o;
    }
    __syncthreads();

    if (tid < 256) {
        const float2 o = sO[tid];
        const float b00 = __ldg(Wb + 0), b01 = __ldg(Wb + 1);
        const float b10 = __ldg(Wb + 2), b11 = __ldg(Wb + 3);
        float2 res;
        res.x = fmaf(o.x, b00, o.y * b10);
        res.y = fmaf(o.x, b01, o.y * b11);
        reinterpret_cast<float2*>(out)[b * CC + r * 256 + tid] = res;
    }
}

extern "C" void kernel_launch(void* const* d_in, const int* in_sizes, int n_in,
                              void* d_out, int out_size)
{
    const float* x  = (const float*)d_in[0];
    const float* Wq = (const float*)d_in[1];
    const float* Wk = (const float*)d_in[2];
    const float* Wv = (const float*)d_in[3];
    const float* Wo = (const float*)d_in[4];
    const float* Wb = (const float*)d_in[5];
    float* out = (float*)d_out;

    k1_moments<<<256, 448>>>(x);
    k2_eval<<<128, 1024>>>(x, Wq, Wk, Wv, Wo, Wb, out);
}

// round 6
// speedup vs baseline: 2.5625x; 1.0928x over previous
#include <cuda_runtime.h>

// B=16, C=2048, H=2, HS=64, HOD=1, D_MODEL=2
// Collapsed: M_h = Wq_h Wk_h^T (2x2), g_h = Wv_h Wo_h (2,)
//   t(c,f) = xp_c^T M_h xp_f / 8  (nats);  o_h(c) = sum_{f<=c} e^t (g_h.xp_f) / sum e^t
// Taylor:  e^{p.y} = sum_{j+i<=12} (p0^j/j!)(p1^i/i!) y0^j y1^i
// => causal sums reduce to prefix moments M_{j,i}(c) = sum_{f<=c} y0^j y1^i.
// K1: per-(batch,chunk64) raw moments (j+i<=13, 105 values) -> global scratch.
// K2: MLP-parallel prefix over 32 chunks, poly eval per query + exact tail (<=64).

#define CC     2048
#define NCHUNK 32
#define CHUNKF 64
#define NMOM   105          // #{(j,i): j+i<=13}
#define LOG2E  1.4426950408889634f

__device__ float g_mom[16][NCHUNK][NMOM];   // raw per-chunk moments

__device__ __forceinline__ int midx(int j, int i) {
    return j * 14 - (j * (j - 1)) / 2 + i;
}

__device__ __forceinline__ float ex2f(float v) {
    float y;
    asm("ex2.approx.ftz.f32 %0, %1;" : "=f"(y) : "f"(v));
    return y;
}

// ---------------- K1: chunk moments ----------------
// grid = 512 (chunk = bid&31, batch = bid>>5), 448 threads (14 warps).
// Warp j accumulates row {(j, i): i <= 13-j}; lane handles 2 f's.
__global__ __launch_bounds__(448, 1)
void k1_moments(const float* __restrict__ x)
{
    const int chunk = blockIdx.x & 31;
    const int b     = blockIdx.x >> 5;
    const int wid   = threadIdx.x >> 5, lane = threadIdx.x & 31;
    const int j     = wid;              // 0..13

    float acc[14];
    #pragma unroll
    for (int i = 0; i < 14; ++i) acc[i] = 0.f;

    #pragma unroll
    for (int ff = 0; ff < 2; ++ff) {
        const int f = chunk * CHUNKF + ff * 32 + lane;
        const float2 v = reinterpret_cast<const float2*>(x)[b * CC + f];
        const float y0 = v.x + sinf((float)f);
        const float y1 = v.y + cosf((float)f);
        float c0 = 1.f;
        for (int jj = 0; jj < j; ++jj) c0 *= y0;   // y0^j
        float vv = c0;
        #pragma unroll
        for (int i = 0; i < 14; ++i) { acc[i] += vv; vv *= y1; }
    }
    #pragma unroll
    for (int i = 0; i < 14; ++i) {
        float s = acc[i];
        #pragma unroll
        for (int off = 16; off; off >>= 1) s += __shfl_down_sync(0xffffffffu, s, off);
        acc[i] = s;
    }
    if (lane == 0) {
        for (int i = 0; i + j <= 13; ++i)
            g_mom[b][chunk][midx(j, i)] = acc[i];
    }
}

// ---------------- K2: evaluation ----------------
// grid = 128 (batch = bid>>3, phase r = bid&7); 1024 threads.
// queries c = 256r .. 256r+255 (= chunks 4r..4r+3).
// sub = tid>>8: {0: h0-poly, 1: h1-poly, 2: h0-tail, 3: h1-tail}
__global__ __launch_bounds__(1024, 1)
void k2_eval(const float* __restrict__ x,
             const float* __restrict__ Wq,
             const float* __restrict__ Wk,
             const float* __restrict__ Wv,
             const float* __restrict__ Wo,
             const float* __restrict__ Wb,
             float* __restrict__ out)
{
    __shared__ float2 sY[256];          // xp for f in [256r, 256r+256)
    __shared__ float  sPre[4][NMOM];    // prefix over chunks < 4r+a, a=0..3
    __shared__ float  sM[2][2][2];      // M[h][i][j]
    __shared__ float  sG[2][2];         // g[h][i]
    __shared__ float4 sPart[256][4];    // per-(c,sub) partials {den, a0, a1}
    __shared__ float2 sO[256];          // o per head

    const int tid = threadIdx.x;
    const int b   = blockIdx.x >> 3;
    const int r   = blockIdx.x & 7;

    // ---- concurrent setup: [0,256) sY | [256,448) dots | [448,553) prefixes ----
    if (tid < 256) {
        const int f = r * 256 + tid;
        const float2 v = reinterpret_cast<const float2*>(x)[b * CC + f];
        sY[tid] = make_float2(v.x + sinf((float)f), v.y + cosf((float)f));
    } else if (tid < 448) {
        const int grp = (tid - 256) >> 4, l16 = tid & 15;
        const float *pa, *pb;
        if (grp < 8) {
            const int h = grp >> 2, i = (grp >> 1) & 1, jj = grp & 1;
            pa = Wq + h * 128 + i * 64;
            pb = Wk + h * 128 + jj * 64;
        } else {
            const int g2 = grp - 8, h = g2 >> 1, i = g2 & 1;
            pa = Wv + h * 128 + i * 64;
            pb = Wo + h * 64;
        }
        float s = 0.f;
        #pragma unroll
        for (int e = 0; e < 4; ++e) s = fmaf(pa[l16 * 4 + e], pb[l16 * 4 + e], s);
        #pragma unroll
        for (int off = 8; off; off >>= 1) s += __shfl_down_sync(0xffffffffu, s, off, 16);
        if (l16 == 0) {
            if (grp < 8) sM[grp >> 2][(grp >> 1) & 1][grp & 1] = s;
            else         sG[(grp - 8) >> 1][(grp - 8) & 1]     = s;
        }
    } else if (tid < 448 + NMOM) {
        // MLP prefix: load ALL 32 chunk values of this moment, then 4 prefixes
        const int m = tid - 448;
        float v[NCHUNK];
        #pragma unroll
        for (int k = 0; k < NCHUNK; ++k) v[k] = g_mom[b][k][m];
        float s = 0.f;
        const int base = 4 * r;
        #pragma unroll
        for (int k = 0; k < NCHUNK; ++k) {   // predicated accumulation
            if (k >= base && k < base + 4) sPre[k - base][m] = s;
            if (k < base + 3) s += v[k];     // only sums actually needed
        }
        if (base + 4 > NCHUNK) { /* unreachable: base<=28 */ }
    }
    __syncthreads();

    const int c_loc = tid & 255;
    const int sub   = tid >> 8;
    const int h     = sub & 1;
    const int type  = sub >> 1;         // 0 = poly, 1 = tail
    const int c     = r * 256 + c_loc;
    const int quad  = c_loc >> 6;       // chunk-within-block 0..3

    const float2 yc = sY[c_loc];
    const float p0 = (sM[h][0][0] * yc.x + sM[h][1][0] * yc.y) * 0.125f;
    const float p1 = (sM[h][0][1] * yc.x + sM[h][1][1] * yc.y) * 0.125f;

    if (type == 0) {
        // polynomial part: sums over f < 64*(4r+quad)
        const float INV[13] = {0.f, 1.f, 0.5f, 1.f/3.f, 0.25f, 0.2f, 1.f/6.f,
                               1.f/7.f, 0.125f, 1.f/9.f, 0.1f, 1.f/11.f, 1.f/12.f};
        float q0[13], q1[13];
        q0[0] = 1.f; q1[0] = 1.f;
        #pragma unroll
        for (int jj = 1; jj < 13; ++jj) {
            q0[jj] = q0[jj - 1] * p0 * INV[jj];
            q1[jj] = q1[jj - 1] * p1 * INV[jj];
        }
        const float* PRE = sPre[quad];
        float sd = 0.f, s0 = 0.f, s1 = 0.f;
        #pragma unroll
        for (int jj = 0; jj <= 12; ++jj) {
            #pragma unroll
            for (int ii = 0; ii + jj <= 12; ++ii) {
                const float w = q0[jj] * q1[ii];
                sd = fmaf(w, PRE[midx(jj, ii)],     sd);
                s0 = fmaf(w, PRE[midx(jj + 1, ii)], s0);
                s1 = fmaf(w, PRE[midx(jj, ii + 1)], s1);
            }
        }
        sPart[c_loc][sub] = make_float4(sd, s0, s1, 0.f);
    } else {
        // exact tail over f in [64*chunk(c), c]  (<= 64 iterations)
        const int fstart = c_loc & ~63;
        const float pd0 = p0 * LOG2E, pd1 = p1 * LOG2E;
        float den = 0.f, a0 = 0.f, a1 = 0.f;
        for (int fl = fstart; fl <= c_loc; ++fl) {
            const float2 yf = sY[fl];
            const float e = ex2f(fmaf(yf.x, pd0, yf.y * pd1));
            den += e;
            a0 = fmaf(e, yf.x, a0);
            a1 = fmaf(e, yf.y, a1);
        }
        sPart[c_loc][sub] = make_float4(den, a0, a1, 0.f);
    }
    __syncthreads();

    if (type == 0) {
        const float4 mine = sPart[c_loc][sub];
        const float4 dd   = sPart[c_loc][2 + h];
        const float den = mine.x + dd.x;
        const float A0  = mine.y + dd.y;
        const float A1  = mine.z + dd.z;
        const float num = sG[h][0] * A0 + sG[h][1] * A1;
        const float o   = num / den;
        if (h == 0) sO[c_loc].x = o; else sO[c_loc].y = o;
    }
    __syncthreads();

    if (tid < 256) {
        const float2 o = sO[tid];
        const float b00 = __ldg(Wb + 0), b01 = __ldg(Wb + 1);
        const float b10 = __ldg(Wb + 2), b11 = __ldg(Wb + 3);
        float2 res;
        res.x = fmaf(o.x, b00, o.y * b10);
        res.y = fmaf(o.x, b01, o.y * b11);
        reinterpret_cast<float2*>(out)[b * CC + r * 256 + tid] = res;
    }
}

extern "C" void kernel_launch(void* const* d_in, const int* in_sizes, int n_in,
                              void* d_out, int out_size)
{
    const float* x  = (const float*)d_in[0];
    const float* Wq = (const float*)d_in[1];
    const float* Wk = (const float*)d_in[2];
    const float* Wv = (const float*)d_in[3];
    const float* Wo = (const float*)d_in[4];
    const float* Wb = (const float*)d_in[5];
    float* out = (float*)d_out;

    k1_moments<<<512, 448>>>(x);
    k2_eval<<<128, 1024>>>(x, Wq, Wk, Wv, Wo, Wb, out);
}